// round 2
// baseline (speedup 1.0000x reference)
#include <cuda_runtime.h>

#define B_    8
#define LQ    4096
#define LK    4096
#define D_    512
#define LSEL  2744
#define SCALE 0.04419417382415922f   // 1/sqrt(512)

// ---------------- scratch (device globals; no allocation allowed) ----------
__device__ float g_kreduce[B_ * D_];
__device__ float g_meanvals[B_ * D_];
__device__ float g_sqk[B_ * LQ];
__device__ float g_thresh[B_];
__device__ int   g_selidx[B_ * LSEL];
__device__ int   g_selcnt[B_];
__device__ float g_S[(size_t)B_ * LSEL * LK];   // ~360 MB score buffer

// ---------------- shared bitonic sort of 4096 floats (ascending) -----------
__device__ __forceinline__ void bitonic4096(float* s) {
    for (int k = 2; k <= 4096; k <<= 1) {
        for (int j = k >> 1; j > 0; j >>= 1) {
            for (int i = threadIdx.x; i < 4096; i += blockDim.x) {
                int ixj = i ^ j;
                if (ixj > i) {
                    float a = s[i], b = s[ixj];
                    if ((a > b) == ((i & k) == 0)) { s[i] = b; s[ixj] = a; }
                }
            }
            __syncthreads();
        }
    }
}

// ---------------- 1. K_reduce: mean of top-LSEL per key column -------------
__global__ void k_kreduce(const float* __restrict__ keys) {
    __shared__ float s[LK];
    __shared__ double red[512];
    int bd = blockIdx.x;            // b*512 + d
    int b = bd >> 9, d = bd & 511;
    const float* kp = keys + (size_t)b * LK * D_ + d;
    for (int i = threadIdx.x; i < LK; i += 512) s[i] = kp[(size_t)i * D_];
    __syncthreads();
    bitonic4096(s);
    double acc = 0.0;
    for (int i = LK - LSEL + threadIdx.x; i < LK; i += 512) acc += (double)s[i];
    red[threadIdx.x] = acc;
    __syncthreads();
    for (int t = 256; t > 0; t >>= 1) {
        if (threadIdx.x < t) red[threadIdx.x] += red[threadIdx.x + t];
        __syncthreads();
    }
    if (threadIdx.x == 0) g_kreduce[bd] = (float)(red[0] / (double)LSEL);
}

// ---------------- 2. mean of values over keys dim ---------------------------
__global__ void k_meanvals(const float* __restrict__ values) {
    int b = blockIdx.x, d = threadIdx.x;
    const float* vp = values + (size_t)b * LK * D_ + d;
    double s = 0.0;
#pragma unroll 8
    for (int k = 0; k < LK; k++) s += (double)vp[(size_t)k * D_];
    g_meanvals[b * D_ + d] = (float)(s / (double)LK);
}

// ---------------- 3. sqk = queries . K_reduce (warp per query) --------------
__global__ void k_sqk(const float* __restrict__ queries) {
    __shared__ float kr[D_];
    int warp = threadIdx.x >> 5, lane = threadIdx.x & 31;
    int qflat = blockIdx.x * 8 + warp;         // 8 queries per block, same batch
    int b = qflat >> 12;
    for (int i = threadIdx.x; i < D_; i += 256) kr[i] = g_kreduce[b * D_ + i];
    __syncthreads();
    const float* qp = queries + (size_t)qflat * D_;
    double acc = 0.0;
#pragma unroll
    for (int j = 0; j < 16; j++) {
        int d = lane + 32 * j;
        acc += (double)qp[d] * (double)kr[d];
    }
    for (int off = 16; off; off >>= 1) acc += __shfl_down_sync(0xffffffffu, acc, off);
    if (lane == 0) g_sqk[qflat] = (float)acc;
}

// ---------------- 4. per-batch selection threshold ---------------------------
__global__ void k_thresh() {
    __shared__ float s[LQ];
    int b = blockIdx.x;
    for (int i = threadIdx.x; i < LQ; i += 512) s[i] = g_sqk[b * LQ + i];
    __syncthreads();
    bitonic4096(s);
    if (threadIdx.x == 0) {
        g_thresh[b] = s[LQ - LSEL];   // 2744th largest
        g_selcnt[b] = 0;
    }
    for (int i = threadIdx.x; i < LSEL; i += 512) g_selidx[b * LSEL + i] = 0;
}

// ---------------- 5. compact selected query indices -------------------------
__global__ void k_compact() {
    int qflat = blockIdx.x * 256 + threadIdx.x;
    int b = qflat >> 12;
    if (g_sqk[qflat] >= g_thresh[b]) {
        int pos = atomicAdd(&g_selcnt[b], 1);
        if (pos < LSEL) g_selidx[b * LSEL + pos] = qflat & 4095;
    }
}

// ---------------- 6. fill unselected rows with mean_values -------------------
__global__ void k_fill(float* __restrict__ out) {
    int r = blockIdx.x;              // b*4096 + q
    int b = r >> 12;
    if (g_sqk[r] < g_thresh[b]) {
        const float4* mv = (const float4*)(g_meanvals + b * D_);
        float4* op = (float4*)(out + (size_t)r * D_);
        op[threadIdx.x] = mv[threadIdx.x];
    }
}

// ---------------- 7. S = scale * Qsel @ K^T  (64x64x16 tiles, 4x4 micro) ----
__global__ void k_gemm_qk(const float* __restrict__ queries,
                          const float* __restrict__ keys) {
    __shared__ float As[16][68];
    __shared__ float Bs[16][68];
    int b = blockIdx.z;
    int m0 = blockIdx.y * 64, n0 = blockIdx.x * 64;
    int tid = threadIdx.x;
    int tx = tid & 15, ty = tid >> 4;
    int lrow = tid >> 2, lc = (tid & 3) * 4;

    int mrow = m0 + lrow;
    int aq = (mrow < LSEL) ? g_selidx[b * LSEL + mrow] : 0;
    const float* ap = queries + ((size_t)b * LQ + aq) * D_;
    const float* bp = keys + ((size_t)b * LK + n0 + lrow) * D_;

    float acc[4][4] = {};
    for (int k0 = 0; k0 < D_; k0 += 16) {
        float4 av = *(const float4*)(ap + k0 + lc);
        float4 bv = *(const float4*)(bp + k0 + lc);
        As[lc + 0][lrow] = av.x; As[lc + 1][lrow] = av.y;
        As[lc + 2][lrow] = av.z; As[lc + 3][lrow] = av.w;
        Bs[lc + 0][lrow] = bv.x; Bs[lc + 1][lrow] = bv.y;
        Bs[lc + 2][lrow] = bv.z; Bs[lc + 3][lrow] = bv.w;
        __syncthreads();
#pragma unroll
        for (int kk = 0; kk < 16; kk++) {
            float a0 = As[kk][ty * 4 + 0], a1 = As[kk][ty * 4 + 1];
            float a2 = As[kk][ty * 4 + 2], a3 = As[kk][ty * 4 + 3];
            float b0 = Bs[kk][tx * 4 + 0], b1 = Bs[kk][tx * 4 + 1];
            float b2 = Bs[kk][tx * 4 + 2], b3 = Bs[kk][tx * 4 + 3];
            acc[0][0] += a0 * b0; acc[0][1] += a0 * b1; acc[0][2] += a0 * b2; acc[0][3] += a0 * b3;
            acc[1][0] += a1 * b0; acc[1][1] += a1 * b1; acc[1][2] += a1 * b2; acc[1][3] += a1 * b3;
            acc[2][0] += a2 * b0; acc[2][1] += a2 * b1; acc[2][2] += a2 * b2; acc[2][3] += a2 * b3;
            acc[3][0] += a3 * b0; acc[3][1] += a3 * b1; acc[3][2] += a3 * b2; acc[3][3] += a3 * b3;
        }
        __syncthreads();
    }
#pragma unroll
    for (int i = 0; i < 4; i++) {
        int row = m0 + ty * 4 + i;
        if (row < LSEL) {
            float* sp = g_S + ((size_t)b * LSEL + row) * LK + n0 + tx * 4;
            sp[0] = acc[i][0] * SCALE; sp[1] = acc[i][1] * SCALE;
            sp[2] = acc[i][2] * SCALE; sp[3] = acc[i][3] * SCALE;
        }
    }
}

// ---------------- 8. row softmax over S (register-resident) -----------------
__global__ void k_softmax() {
    __shared__ float red[256];
    size_t r = blockIdx.x;
    float4* sp4 = (float4*)(g_S + r * LK);
    int tid = threadIdx.x;
    float v[16];
    float mx = -1e30f;
#pragma unroll
    for (int j = 0; j < 4; j++) {
        float4 t = sp4[tid + 256 * j];
        v[4 * j + 0] = t.x; v[4 * j + 1] = t.y; v[4 * j + 2] = t.z; v[4 * j + 3] = t.w;
        mx = fmaxf(mx, fmaxf(fmaxf(t.x, t.y), fmaxf(t.z, t.w)));
    }
    red[tid] = mx; __syncthreads();
    for (int t = 128; t > 0; t >>= 1) {
        if (tid < t) red[tid] = fmaxf(red[tid], red[tid + t]);
        __syncthreads();
    }
    mx = red[0]; __syncthreads();
    float s = 0.f;
#pragma unroll
    for (int i = 0; i < 16; i++) { v[i] = expf(v[i] - mx); s += v[i]; }
    red[tid] = s; __syncthreads();
    for (int t = 128; t > 0; t >>= 1) {
        if (tid < t) red[tid] += red[tid + t];
        __syncthreads();
    }
    float inv = 1.0f / red[0];
#pragma unroll
    for (int j = 0; j < 4; j++) {
        float4 t;
        t.x = v[4 * j + 0] * inv; t.y = v[4 * j + 1] * inv;
        t.z = v[4 * j + 2] * inv; t.w = v[4 * j + 3] * inv;
        sp4[tid + 256 * j] = t;
    }
}

// ---------------- 9. O = P @ V, scatter epilogue -----------------------------
__global__ void k_gemm_pv(const float* __restrict__ values,
                          float* __restrict__ out) {
    __shared__ float As[16][68];
    __shared__ float Bs[16][64];
    int b = blockIdx.z;
    int m0 = blockIdx.y * 64, n0 = blockIdx.x * 64;
    int tid = threadIdx.x;
    int tx = tid & 15, ty = tid >> 4;
    int lrowA = tid >> 2, lcA = (tid & 3) * 4;
    int krow = tid >> 4, nc = (tid & 15) * 4;

    int mrow = m0 + lrowA;
    int mclamp = (mrow < LSEL) ? mrow : (LSEL - 1);
    const float* ap = g_S + ((size_t)b * LSEL + mclamp) * LK;

    float acc[4][4] = {};
    for (int k0 = 0; k0 < LK; k0 += 16) {
        float4 av = *(const float4*)(ap + k0 + lcA);
        As[lcA + 0][lrowA] = av.x; As[lcA + 1][lrowA] = av.y;
        As[lcA + 2][lrowA] = av.z; As[lcA + 3][lrowA] = av.w;
        float4 bv = *(const float4*)(values + ((size_t)b * LK + k0 + krow) * D_ + n0 + nc);
        *(float4*)&Bs[krow][nc] = bv;
        __syncthreads();
#pragma unroll
        for (int kk = 0; kk < 16; kk++) {
            float a0 = As[kk][ty * 4 + 0], a1 = As[kk][ty * 4 + 1];
            float a2 = As[kk][ty * 4 + 2], a3 = As[kk][ty * 4 + 3];
            float b0 = Bs[kk][tx * 4 + 0], b1 = Bs[kk][tx * 4 + 1];
            float b2 = Bs[kk][tx * 4 + 2], b3 = Bs[kk][tx * 4 + 3];
            acc[0][0] += a0 * b0; acc[0][1] += a0 * b1; acc[0][2] += a0 * b2; acc[0][3] += a0 * b3;
            acc[1][0] += a1 * b0; acc[1][1] += a1 * b1; acc[1][2] += a1 * b2; acc[1][3] += a1 * b3;
            acc[2][0] += a2 * b0; acc[2][1] += a2 * b1; acc[2][2] += a2 * b2; acc[2][3] += a2 * b3;
            acc[3][0] += a3 * b0; acc[3][1] += a3 * b1; acc[3][2] += a3 * b2; acc[3][3] += a3 * b3;
        }
        __syncthreads();
    }
#pragma unroll
    for (int i = 0; i < 4; i++) {
        int row = m0 + ty * 4 + i;
        if (row < LSEL) {
            int q = g_selidx[b * LSEL + row];
            float* op = out + ((size_t)b * LQ + q) * D_ + n0 + tx * 4;
            op[0] = acc[i][0]; op[1] = acc[i][1];
            op[2] = acc[i][2]; op[3] = acc[i][3];
        }
    }
}

// ---------------- launch ------------------------------------------------------
extern "C" void kernel_launch(void* const* d_in, const int* in_sizes, int n_in,
                              void* d_out, int out_size) {
    const float* q = (const float*)d_in[0];
    const float* k = (const float*)d_in[1];
    const float* v = (const float*)d_in[2];
    float* out = (float*)d_out;

    k_kreduce<<<B_ * D_, 512>>>(k);
    k_meanvals<<<B_, 512>>>(v);
    k_sqk<<<B_ * LQ / 8, 256>>>(q);
    k_thresh<<<B_, 512>>>();
    k_compact<<<B_ * LQ / 256, 256>>>();
    k_fill<<<B_ * LQ, 128>>>(out);

    dim3 g1(LK / 64, (LSEL + 63) / 64, B_);
    k_gemm_qk<<<g1, 256>>>(q, k);

    k_softmax<<<B_ * LSEL, 256>>>();

    dim3 g2(D_ / 64, (LSEL + 63) / 64, B_);
    k_gemm_pv<<<g2, 256>>>(v, out);
}

// round 4
// speedup vs baseline: 3.5552x; 3.5552x over previous
#include <cuda_runtime.h>
#include <cuda_bf16.h>
#include <cstdint>

#define B_    8
#define LQ    4096
#define LK    4096
#define D_    512
#define LSEL  2744
#define MPAD  2816
#define SCALE 0.04419417382415922f   // 1/sqrt(512)

// ============================ device scratch ================================
__device__ __nv_bfloat16 g_qh[B_ * LQ * D_];    // Q*SCALE hi
__device__ __nv_bfloat16 g_ql[B_ * LQ * D_];    // Q*SCALE lo
__device__ __nv_bfloat16 g_kh[B_ * LK * D_];
__device__ __nv_bfloat16 g_kl[B_ * LK * D_];
__device__ __nv_bfloat16 g_vth[B_ * D_ * LK];   // V^T hi  [b][d][k]
__device__ __nv_bfloat16 g_vtl[B_ * D_ * LK];   // V^T lo
__device__ __nv_bfloat16 g_ph[(size_t)B_ * MPAD * LK];  // P hi [b][m][k]
__device__ __nv_bfloat16 g_pl[(size_t)B_ * MPAD * LK];  // P lo
__device__ float  g_S[(size_t)B_ * LSEL * LK];  // fp32 scores (scaled)
__device__ float  g_kreduce[B_ * D_];
__device__ double g_meanpart[B_ * 32 * D_];
__device__ float  g_meanvals[B_ * D_];
__device__ float  g_sqk[B_ * LQ];
__device__ float  g_thresh[B_];
__device__ int    g_selidx[B_ * LSEL];
__device__ int    g_selcnt[B_];

// ============================ PTX helpers ===================================
__device__ __forceinline__ uint32_t smem_u32(const void* p) {
    uint32_t a;
    asm("{ .reg .u64 t; cvta.to.shared.u64 t, %1; cvt.u32.u64 %0, t; }" : "=r"(a) : "l"(p));
    return a;
}

#define CP_ASYNC16(dst, src) \
    asm volatile("cp.async.cg.shared.global [%0], [%1], 16;" :: "r"(dst), "l"(src) : "memory")
#define CP_COMMIT() asm volatile("cp.async.commit_group;" ::: "memory")
#define CP_WAIT2()  asm volatile("cp.async.wait_group 2;" ::: "memory")
#define CP_WAIT0()  asm volatile("cp.async.wait_group 0;" ::: "memory")

#define LDSM4(r, a) \
    asm volatile("ldmatrix.sync.aligned.m8n8.x4.shared.b16 {%0,%1,%2,%3}, [%4];" \
        : "=r"((r)[0]), "=r"((r)[1]), "=r"((r)[2]), "=r"((r)[3]) : "r"(a))

#define MMA16816(d, a, b0, b1) \
    asm volatile("mma.sync.aligned.m16n8k16.row.col.f32.bf16.bf16.f32 " \
        "{%0,%1,%2,%3}, {%4,%5,%6,%7}, {%8,%9}, {%0,%1,%2,%3};" \
        : "+f"((d)[0]), "+f"((d)[1]), "+f"((d)[2]), "+f"((d)[3]) \
        : "r"((a)[0]), "r"((a)[1]), "r"((a)[2]), "r"((a)[3]), "r"(b0), "r"(b1))

// swizzled addr inside one 128-row x 128-byte tile
__device__ __forceinline__ uint32_t swaddr(uint32_t base, int row, int kb) {
    uint32_t o = (uint32_t)(row * 128 + kb);
    return base + (o ^ ((o >> 3) & 0x70));
}

__device__ __forceinline__ unsigned f2sort(float f) {
    unsigned u = __float_as_uint(f);
    return (u & 0x80000000u) ? ~u : (u | 0x80000000u);
}
__device__ __forceinline__ float sort2f(unsigned u) {
    unsigned fb = (u & 0x80000000u) ? (u ^ 0x80000000u) : ~u;
    return __uint_as_float(fb);
}

// =================== split fp32 -> bf16 hi/lo (Q scaled, K) =================
__global__ void k_split(const float4* __restrict__ src, int sel, float scale) {
    size_t i = (size_t)blockIdx.x * 256 + threadIdx.x;
    float4 v = src[i];
    v.x *= scale; v.y *= scale; v.z *= scale; v.w *= scale;
    __nv_bfloat162* dh = (__nv_bfloat162*)(sel ? g_kh : g_qh);
    __nv_bfloat162* dl = (__nv_bfloat162*)(sel ? g_kl : g_ql);
    __nv_bfloat16 h0 = __float2bfloat16(v.x), h1 = __float2bfloat16(v.y);
    __nv_bfloat16 h2 = __float2bfloat16(v.z), h3 = __float2bfloat16(v.w);
    __nv_bfloat16 l0 = __float2bfloat16(v.x - __bfloat162float(h0));
    __nv_bfloat16 l1 = __float2bfloat16(v.y - __bfloat162float(h1));
    __nv_bfloat16 l2 = __float2bfloat16(v.z - __bfloat162float(h2));
    __nv_bfloat16 l3 = __float2bfloat16(v.w - __bfloat162float(h3));
    dh[2 * i]     = __nv_bfloat162{h0, h1};
    dh[2 * i + 1] = __nv_bfloat162{h2, h3};
    dl[2 * i]     = __nv_bfloat162{l0, l1};
    dl[2 * i + 1] = __nv_bfloat162{l2, l3};
}

// =================== V transpose + split -> VT hi/lo ========================
__global__ void k_split_vt(const float* __restrict__ v) {
    __shared__ float t[32][33];
    int b = blockIdx.z, d0 = blockIdx.x * 32, k0 = blockIdx.y * 32;
    int tx = threadIdx.x, ty = threadIdx.y;
#pragma unroll
    for (int j = 0; j < 4; j++)
        t[ty + 8 * j][tx] = v[((size_t)b * LK + k0 + ty + 8 * j) * D_ + d0 + tx];
    __syncthreads();
#pragma unroll
    for (int j = 0; j < 4; j++) {
        float f = t[tx][ty + 8 * j];
        __nv_bfloat16 h = __float2bfloat16(f);
        __nv_bfloat16 l = __float2bfloat16(f - __bfloat162float(h));
        size_t o = ((size_t)b * D_ + d0 + ty + 8 * j) * LK + k0 + tx;
        g_vth[o] = h;
        g_vtl[o] = l;
    }
}

// =================== radix select: k-th largest of 4096 =====================
__device__ void radix_select(unsigned* su, unsigned* hist,
                             unsigned* s_pref, unsigned* s_need, int want) {
    int tid = threadIdx.x;
    if (tid == 0) { *s_pref = 0; *s_need = (unsigned)want; }
    __syncthreads();
    unsigned pref = 0, need = (unsigned)want;
    for (int pass = 3; pass >= 0; pass--) {
        if (tid < 256) hist[tid] = 0;
        __syncthreads();
        for (int i = tid; i < 4096; i += 256) {
            unsigned u = su[i];
            unsigned hi = (pass == 3) ? 0u : (u >> ((pass + 1) * 8));
            if (hi == pref) atomicAdd(&hist[(u >> (pass * 8)) & 255], 1);
        }
        __syncthreads();
        if (tid == 0) {
            unsigned cum = 0;
            for (int bin = 255; bin >= 0; bin--) {
                unsigned c = hist[bin];
                if (cum + c >= need) {
                    *s_need = need - cum;
                    *s_pref = (pref << 8) | (unsigned)bin;
                    break;
                }
                cum += c;
            }
        }
        __syncthreads();
        pref = *s_pref; need = *s_need;
        __syncthreads();
    }
}

// =================== K_reduce: mean of top-LSEL per key column ==============
__global__ void k_kreduce(const float* __restrict__ keys) {
    __shared__ unsigned su[4096];
    __shared__ unsigned hist[256];
    __shared__ unsigned s_pref, s_need;
    __shared__ double red[256];
    int bd = blockIdx.x, b = bd >> 9, d = bd & 511;
    int tid = threadIdx.x;
    const float* kp = keys + (size_t)b * LK * D_ + d;
    for (int i = tid; i < 4096; i += 256) su[i] = f2sort(kp[(size_t)i * D_]);
    __syncthreads();
    radix_select(su, hist, &s_pref, &s_need, LSEL);
    unsigned tu = s_pref, need = s_need;
    double acc = 0.0;
    for (int i = tid; i < 4096; i += 256)
        if (su[i] > tu) acc += (double)sort2f(su[i]);
    red[tid] = acc;
    __syncthreads();
    for (int t = 128; t > 0; t >>= 1) {
        if (tid < t) red[tid] += red[tid + t];
        __syncthreads();
    }
    if (tid == 0)
        g_kreduce[bd] = (float)((red[0] + (double)need * (double)sort2f(tu)) / (double)LSEL);
}

// =================== value means ============================================
__global__ void k_meanpart(const float* __restrict__ values) {
    int b = blockIdx.y, j = blockIdx.x, d = threadIdx.x;
    const float* vp = values + ((size_t)b * LK + j * 128) * D_ + d;
    double s = 0.0;
#pragma unroll 8
    for (int r = 0; r < 128; r++) s += (double)vp[(size_t)r * D_];
    g_meanpart[((size_t)b * 32 + j) * D_ + d] = s;
}
__global__ void k_meanfin() {
    int b = blockIdx.x, d = threadIdx.x;
    double s = 0.0;
    for (int j = 0; j < 32; j++) s += g_meanpart[((size_t)b * 32 + j) * D_ + d];
    g_meanvals[b * D_ + d] = (float)(s / (double)LK);
}

// =================== sqk = Q . K_reduce (fp64) ===============================
__global__ void k_sqk(const float* __restrict__ queries) {
    __shared__ float kr[D_];
    int warp = threadIdx.x >> 5, lane = threadIdx.x & 31;
    int qflat = blockIdx.x * 8 + warp;
    int b = qflat >> 12;
    for (int i = threadIdx.x; i < D_; i += 256) kr[i] = g_kreduce[b * D_ + i];
    __syncthreads();
    const float* qp = queries + (size_t)qflat * D_;
    double acc = 0.0;
#pragma unroll
    for (int j = 0; j < 16; j++) {
        int d = lane + 32 * j;
        acc += (double)qp[d] * (double)kr[d];
    }
    for (int off = 16; off; off >>= 1) acc += __shfl_down_sync(0xffffffffu, acc, off);
    if (lane == 0) g_sqk[qflat] = (float)acc;
}

// =================== selection threshold (exact radix) ======================
__global__ void k_thresh() {
    __shared__ unsigned su[4096];
    __shared__ unsigned hist[256];
    __shared__ unsigned s_pref, s_need;
    int b = blockIdx.x, tid = threadIdx.x;
    for (int i = tid; i < 4096; i += 256) su[i] = f2sort(g_sqk[b * LQ + i]);
    __syncthreads();
    radix_select(su, hist, &s_pref, &s_need, LSEL);
    if (tid == 0) {
        g_thresh[b] = sort2f(s_pref);
        g_selcnt[b] = 0;
    }
}

__global__ void k_compact() {
    int qflat = blockIdx.x * 256 + threadIdx.x;
    int b = qflat >> 12;
    if (g_sqk[qflat] >= g_thresh[b]) {
        int pos = atomicAdd(&g_selcnt[b], 1);
        if (pos < LSEL) g_selidx[b * LSEL + pos] = qflat & 4095;
    }
}

__global__ void k_fill(float* __restrict__ out) {
    int r = blockIdx.x, b = r >> 12;
    if (g_sqk[r] < g_thresh[b]) {
        const float4* mv = (const float4*)(g_meanvals + b * D_);
        float4* op = (float4*)(out + (size_t)r * D_);
        op[threadIdx.x] = mv[threadIdx.x];
    }
}

// =================== shared mma.sync tile compute ===========================
// stage layout: Ah @0, Al @16K, Bh @32K, Bl @48K (each 128 rows x 128B, SW128)
// warp grid 4(M) x 2(N); warp tile 32x64; acc d[2 mtiles][8 ntiles][4]
__device__ __forceinline__ void gemm_stage(uint32_t st, int wm, int wn, int lane,
                                           float d[2][8][4]) {
    int rA = wm * 32 + (lane & 15);
    int kA = (lane >> 4) * 16;
    int rB = wn * 64 + (lane & 7) + ((lane >> 4) << 3);
    int kB = ((lane >> 3) & 1) * 16;
#pragma unroll
    for (int t = 0; t < 4; t++) {
        uint32_t ah[2][4], al[2][4];
        LDSM4(ah[0], swaddr(st, rA, t * 32 + kA));
        LDSM4(ah[1], swaddr(st, rA + 16, t * 32 + kA));
        LDSM4(al[0], swaddr(st + 16384, rA, t * 32 + kA));
        LDSM4(al[1], swaddr(st + 16384, rA + 16, t * 32 + kA));
#pragma unroll
        for (int p = 0; p < 4; p++) {
            uint32_t bh[4], bl[4];
            LDSM4(bh, swaddr(st + 32768, rB + p * 16, t * 32 + kB));
            LDSM4(bl, swaddr(st + 49152, rB + p * 16, t * 32 + kB));
#pragma unroll
            for (int i = 0; i < 2; i++) {
                MMA16816(d[i][2 * p],     ah[i], bh[0], bh[1]);
                MMA16816(d[i][2 * p + 1], ah[i], bh[2], bh[3]);
                MMA16816(d[i][2 * p],     ah[i], bl[0], bl[1]);
                MMA16816(d[i][2 * p + 1], ah[i], bl[2], bl[3]);
                MMA16816(d[i][2 * p],     al[i], bh[0], bh[1]);
                MMA16816(d[i][2 * p + 1], al[i], bh[2], bh[3]);
            }
        }
    }
}

#define SMEM_DYN (3 * 65536)

// =================== GEMM 1: S = Qsel(scaled) @ K^T =========================
__global__ void __launch_bounds__(256, 1) k_gemm_qk() {
    extern __shared__ char dsm[];
    __shared__ int srow[128];
    uint32_t sb = smem_u32(dsm);
    int tid = threadIdx.x;
    int b = blockIdx.z, m0 = blockIdx.y * 128, n0 = blockIdx.x * 128;

    if (tid < 128) {
        int m = m0 + tid;
        srow[tid] = g_selidx[b * LSEL + (m < LSEL ? m : 0)];
    }
    __syncthreads();

    const __nv_bfloat16* baseA[2] = { g_qh + (size_t)b * LQ * D_,
                                      g_ql + (size_t)b * LQ * D_ };
    const __nv_bfloat16* baseB[2] = { g_kh + ((size_t)b * LK + n0) * D_,
                                      g_kl + ((size_t)b * LK + n0) * D_ };

#define QK_FILL(s, k) do {                                                     \
    uint32_t st_ = sb + (s) * 65536;                                           \
    int k0_ = (k) * 64;                                                        \
    for (int idx = tid; idx < 4096; idx += 256) {                              \
        int tile_ = idx >> 10, r_ = (idx >> 3) & 127, seg_ = idx & 7;          \
        const __nv_bfloat16* src_;                                             \
        if (tile_ < 2) src_ = baseA[tile_] + (size_t)srow[r_] * D_ + k0_ + seg_ * 8; \
        else           src_ = baseB[tile_ - 2] + (size_t)r_ * D_ + k0_ + seg_ * 8;   \
        CP_ASYNC16(swaddr(st_ + tile_ * 16384, r_, seg_ * 16), src_);          \
    } CP_COMMIT(); } while (0)

    QK_FILL(0, 0); QK_FILL(1, 1); QK_FILL(2, 2);

    int lane = tid & 31, w = tid >> 5, wm = w >> 1, wn = w & 1;
    float d[2][8][4] = {};

    for (int k = 0; k < 8; k++) {
        int s = k % 3;
        if (k == 7) { CP_WAIT0(); } else { CP_WAIT2(); }
        __syncthreads();
        gemm_stage(sb + s * 65536, wm, wn, lane, d);
        __syncthreads();
        if (k + 3 < 8) QK_FILL(s, k + 3);
    }

    int mBase = m0 + wm * 32, nBase = n0 + wn * 64;
#pragma unroll
    for (int i = 0; i < 2; i++) {
        int r = mBase + i * 16 + (lane >> 2);
#pragma unroll
        for (int j = 0; j < 8; j++) {
            int c = nBase + j * 8 + (lane & 3) * 2;
            if (r < LSEL)
                *(float2*)(g_S + ((size_t)b * LSEL + r) * LK + c) =
                    float2{d[i][j][0], d[i][j][1]};
            if (r + 8 < LSEL)
                *(float2*)(g_S + ((size_t)b * LSEL + r + 8) * LK + c) =
                    float2{d[i][j][2], d[i][j][3]};
        }
    }
}

// =================== softmax -> P hi/lo bf16 ================================
__global__ void k_softmax() {
    __shared__ float red[256];
    int blk = blockIdx.x;
    int b = blk / LSEL, m = blk - b * LSEL;
    const float4* sp4 = (const float4*)(g_S + ((size_t)b * LSEL + m) * LK);
    size_t po = ((size_t)b * MPAD + m) * LK;
    int tid = threadIdx.x;
    float v[16];
    float mx = -1e30f;
#pragma unroll
    for (int j = 0; j < 4; j++) {
        float4 t = sp4[tid + 256 * j];
        v[4 * j + 0] = t.x; v[4 * j + 1] = t.y; v[4 * j + 2] = t.z; v[4 * j + 3] = t.w;
        mx = fmaxf(mx, fmaxf(fmaxf(t.x, t.y), fmaxf(t.z, t.w)));
    }
    red[tid] = mx; __syncthreads();
    for (int t = 128; t > 0; t >>= 1) {
        if (tid < t) red[tid] = fmaxf(red[tid], red[tid + t]);
        __syncthreads();
    }
    mx = red[0]; __syncthreads();
    float s = 0.f;
#pragma unroll
    for (int i = 0; i < 16; i++) { v[i] = expf(v[i] - mx); s += v[i]; }
    red[tid] = s; __syncthreads();
    for (int t = 128; t > 0; t >>= 1) {
        if (tid < t) red[tid] += red[tid + t];
        __syncthreads();
    }
    float inv = 1.0f / red[0];
#pragma unroll
    for (int j = 0; j < 4; j++) {
        int col = (tid + 256 * j) * 4;
        __nv_bfloat16 h[4], l[4];
#pragma unroll
        for (int i = 0; i < 4; i++) {
            float f = v[4 * j + i] * inv;
            h[i] = __float2bfloat16(f);
            l[i] = __float2bfloat16(f - __bfloat162float(h[i]));
        }
        *(__nv_bfloat162*)(g_ph + po + col)     = __nv_bfloat162{h[0], h[1]};
        *(__nv_bfloat162*)(g_ph + po + col + 2) = __nv_bfloat162{h[2], h[3]};
        *(__nv_bfloat162*)(g_pl + po + col)     = __nv_bfloat162{l[0], l[1]};
        *(__nv_bfloat162*)(g_pl + po + col + 2) = __nv_bfloat162{l[2], l[3]};
    }
}

// =================== GEMM 2: O = P @ V, scatter =============================
__global__ void __launch_bounds__(256, 1) k_gemm_pv(float* __restrict__ out) {
    extern __shared__ char dsm[];
    __shared__ int srow[128];
    uint32_t sb = smem_u32(dsm);
    int tid = threadIdx.x;
    int b = blockIdx.z, m0 = blockIdx.y * 128, n0 = blockIdx.x * 128;

    if (tid < 128) {
        int m = m0 + tid;
        srow[tid] = g_selidx[b * LSEL + (m < LSEL ? m : 0)];
    }
    __syncthreads();

    const __nv_bfloat16* baseA[2] = { g_ph + ((size_t)b * MPAD + m0) * LK,
                                      g_pl + ((size_t)b * MPAD + m0) * LK };
    const __nv_bfloat16* baseB[2] = { g_vth + ((size_t)b * D_ + n0) * LK,
                                      g_vtl + ((size_t)b * D_ + n0) * LK };

#define PV_FILL(s, k) do {                                                     \
    uint32_t st_ = sb + (s) * 65536;                                           \
    int k0_ = (k) * 64;                                                        \
    for (int idx = tid; idx < 4096; idx += 256) {                              \
        int tile_ = idx >> 10, r_ = (idx >> 3) & 127, seg_ = idx & 7;          \
        const __nv_bfloat16* src_;                                             \
        if (tile_ < 2) src_ = baseA[tile_] + (size_t)r_ * LK + k0_ + seg_ * 8; \
        else           src_ = baseB[tile_ - 2] + (size_t)r_ * LK + k0_ + seg_ * 8; \
        CP_ASYNC16(swaddr(st_ + tile_ * 16384, r_, seg_ * 16), src_);          \
    } CP_COMMIT(); } while (0)

    PV_FILL(0, 0); PV_FILL(1, 1); PV_FILL(2, 2);

    int lane = tid & 31, w = tid >> 5, wm = w >> 1, wn = w & 1;
    float d[2][8][4] = {};

    for (int k = 0; k < 64; k++) {
        int s = k % 3;
        if (k == 63) { CP_WAIT0(); } else { CP_WAIT2(); }
        __syncthreads();
        gemm_stage(sb + s * 65536, wm, wn, lane, d);
        __syncthreads();
        if (k + 3 < 64) PV_FILL(s, k + 3);
    }

    int nBase = n0 + wn * 64;
#pragma unroll
    for (int i = 0; i < 2; i++) {
        int lr = wm * 32 + i * 16 + (lane >> 2);
        int m = m0 + lr;
        int q0 = srow[lr], q1 = srow[lr + 8];
#pragma unroll
        for (int j = 0; j < 8; j++) {
            int c = nBase + j * 8 + (lane & 3) * 2;
            if (m < LSEL)
                *(float2*)(out + ((size_t)b * LQ + q0) * D_ + c) =
                    float2{d[i][j][0], d[i][j][1]};
            if (m + 8 < LSEL)
                *(float2*)(out + ((size_t)b * LQ + q1) * D_ + c) =
                    float2{d[i][j][2], d[i][j][3]};
        }
    }
}

// =================== launch ==================================================
extern "C" void kernel_launch(void* const* d_in, const int* in_sizes, int n_in,
                              void* d_out, int out_size) {
    const float* q = (const float*)d_in[0];
    const float* k = (const float*)d_in[1];
    const float* v = (const float*)d_in[2];
    float* out = (float*)d_out;

    cudaFuncSetAttribute(k_gemm_qk, cudaFuncAttributeMaxDynamicSharedMemorySize, SMEM_DYN);
    cudaFuncSetAttribute(k_gemm_pv, cudaFuncAttributeMaxDynamicSharedMemorySize, SMEM_DYN);

    k_split<<<16384, 256>>>((const float4*)q, 0, SCALE);
    k_split<<<16384, 256>>>((const float4*)k, 1, 1.0f);
    k_split_vt<<<dim3(16, 128, 8), dim3(32, 8)>>>(v);

    k_kreduce<<<B_ * D_, 256>>>(k);
    k_meanpart<<<dim3(32, B_), 512>>>(v);
    k_meanfin<<<B_, 512>>>();
    k_sqk<<<B_ * LQ / 8, 256>>>(q);
    k_thresh<<<B_, 256>>>();
    k_compact<<<B_ * LQ / 256, 256>>>();
    k_fill<<<B_ * LQ, 128>>>(out);

    dim3 g1(LK / 128, (LSEL + 127) / 128, B_);   // 32 x 22 x 8
    k_gemm_qk<<<g1, 256, SMEM_DYN>>>();

    k_softmax<<<B_ * LSEL, 256>>>();

    dim3 g2(D_ / 128, (LSEL + 127) / 128, B_);   // 4 x 22 x 8
    k_gemm_pv<<<g2, 256, SMEM_DYN>>>(out);
}

// round 5
// speedup vs baseline: 4.1763x; 1.1747x over previous
#include <cuda_runtime.h>
#include <cuda_fp16.h>
#include <cstdint>

#define B_    8
#define LQ    4096
#define LK    4096
#define D_    512
#define LSEL  2744
#define MPAD  2816
#define SCALE 0.04419417382415922f   // 1/sqrt(512)

// ============================ device scratch ================================
__device__ __half g_qh[B_ * LQ * D_];           // Q*SCALE fp16
__device__ __half g_kh[B_ * LK * D_];           // K hi fp16
__device__ __half g_kl[B_ * LK * D_];           // K lo fp16
__device__ __half g_vth[B_ * D_ * LK];          // V^T hi fp16 [b][d][k]
__device__ __half g_vtl[B_ * D_ * LK];          // V^T lo fp16
__device__ __half g_E[(size_t)B_ * MPAD * LK];  // exp(S) fp16 [b][m][k]
__device__ float  g_kt[(size_t)B_ * D_ * LK];   // K^T fp32 [b][d][k]
__device__ float  g_Zpart[B_ * MPAD * 32];
__device__ float  g_Z[B_ * MPAD];
__device__ float  g_kreduce[B_ * D_];
__device__ double g_meanpart[B_ * 32 * D_];
__device__ float  g_meanvals[B_ * D_];
__device__ float  g_sqk[B_ * LQ];
__device__ float  g_thresh[B_];
__device__ int    g_selidx[B_ * LSEL];
__device__ int    g_selcnt[B_];

// ============================ PTX helpers ===================================
__device__ __forceinline__ uint32_t smem_u32(const void* p) {
    uint32_t a;
    asm("{ .reg .u64 t; cvta.to.shared.u64 t, %1; cvt.u32.u64 %0, t; }" : "=r"(a) : "l"(p));
    return a;
}

#define CP_ASYNC16(dst, src) \
    asm volatile("cp.async.cg.shared.global [%0], [%1], 16;" :: "r"(dst), "l"(src) : "memory")
#define CP_COMMIT() asm volatile("cp.async.commit_group;" ::: "memory")
#define CP_WAIT2()  asm volatile("cp.async.wait_group 2;" ::: "memory")
#define CP_WAIT0()  asm volatile("cp.async.wait_group 0;" ::: "memory")

#define LDSM4(r, a) \
    asm volatile("ldmatrix.sync.aligned.m8n8.x4.shared.b16 {%0,%1,%2,%3}, [%4];" \
        : "=r"((r)[0]), "=r"((r)[1]), "=r"((r)[2]), "=r"((r)[3]) : "r"(a))

#define MMAH(d, a, b0, b1) \
    asm volatile("mma.sync.aligned.m16n8k16.row.col.f32.f16.f16.f32 " \
        "{%0,%1,%2,%3}, {%4,%5,%6,%7}, {%8,%9}, {%0,%1,%2,%3};" \
        : "+f"((d)[0]), "+f"((d)[1]), "+f"((d)[2]), "+f"((d)[3]) \
        : "r"((a)[0]), "r"((a)[1]), "r"((a)[2]), "r"((a)[3]), "r"(b0), "r"(b1))

// swizzled addr inside one 128-row x 128-byte tile (SW128)
__device__ __forceinline__ uint32_t swaddr(uint32_t base, int row, int kb) {
    uint32_t o = (uint32_t)(row * 128 + kb);
    return base + (o ^ ((o >> 3) & 0x70));
}

__device__ __forceinline__ unsigned f2sort(float f) {
    unsigned u = __float_as_uint(f);
    return (u & 0x80000000u) ? ~u : (u | 0x80000000u);
}
__device__ __forceinline__ float sort2f(unsigned u) {
    unsigned fb = (u & 0x80000000u) ? (u ^ 0x80000000u) : ~u;
    return __uint_as_float(fb);
}

// =================== splits ==================================================
__global__ void k_split_q(const float4* __restrict__ src) {
    size_t i = (size_t)blockIdx.x * 256 + threadIdx.x;
    float4 v = src[i];
    __half2* dh = (__half2*)g_qh;
    dh[2 * i]     = __floats2half2_rn(v.x * SCALE, v.y * SCALE);
    dh[2 * i + 1] = __floats2half2_rn(v.z * SCALE, v.w * SCALE);
}

__global__ void k_split_k(const float4* __restrict__ src) {
    size_t i = (size_t)blockIdx.x * 256 + threadIdx.x;
    float4 v = src[i];
    __half h0 = __float2half_rn(v.x), h1 = __float2half_rn(v.y);
    __half h2 = __float2half_rn(v.z), h3 = __float2half_rn(v.w);
    ((__half2*)g_kh)[2 * i]     = __half2{h0, h1};
    ((__half2*)g_kh)[2 * i + 1] = __half2{h2, h3};
    ((__half2*)g_kl)[2 * i] = __floats2half2_rn(v.x - __half2float(h0), v.y - __half2float(h1));
    ((__half2*)g_kl)[2 * i + 1] = __floats2half2_rn(v.z - __half2float(h2), v.w - __half2float(h3));
}

__global__ void k_split_vt(const float* __restrict__ v) {
    __shared__ float t[32][33];
    int b = blockIdx.z, d0 = blockIdx.x * 32, k0 = blockIdx.y * 32;
    int tx = threadIdx.x, ty = threadIdx.y;
#pragma unroll
    for (int j = 0; j < 4; j++)
        t[ty + 8 * j][tx] = v[((size_t)b * LK + k0 + ty + 8 * j) * D_ + d0 + tx];
    __syncthreads();
#pragma unroll
    for (int j = 0; j < 4; j++) {
        float f = t[tx][ty + 8 * j];
        __half h = __float2half_rn(f);
        size_t o = ((size_t)b * D_ + d0 + ty + 8 * j) * LK + k0 + tx;
        g_vth[o] = h;
        g_vtl[o] = __float2half_rn(f - __half2float(h));
    }
}

__global__ void k_transpose(const float* __restrict__ keys) {
    __shared__ float t[32][33];
    int b = blockIdx.z, d0 = blockIdx.x * 32, k0 = blockIdx.y * 32;
    int tx = threadIdx.x, ty = threadIdx.y;
#pragma unroll
    for (int j = 0; j < 4; j++)
        t[ty + 8 * j][tx] = keys[((size_t)b * LK + k0 + ty + 8 * j) * D_ + d0 + tx];
    __syncthreads();
#pragma unroll
    for (int j = 0; j < 4; j++)
        g_kt[((size_t)b * D_ + d0 + ty + 8 * j) * LK + k0 + tx] = t[tx][ty + 8 * j];
}

// =================== radix select: k-th largest of 4096 =====================
__device__ void radix_select(unsigned* su, unsigned* hist,
                             unsigned* s_pref, unsigned* s_need, int want) {
    int tid = threadIdx.x;
    if (tid == 0) { *s_pref = 0; *s_need = (unsigned)want; }
    __syncthreads();
    unsigned pref = 0, need = (unsigned)want;
    for (int pass = 3; pass >= 0; pass--) {
        if (tid < 256) hist[tid] = 0;
        __syncthreads();
        for (int i = tid; i < 4096; i += 256) {
            unsigned u = su[i];
            unsigned hi = (pass == 3) ? 0u : (u >> ((pass + 1) * 8));
            if (hi == pref) atomicAdd(&hist[(u >> (pass * 8)) & 255], 1);
        }
        __syncthreads();
        if (tid == 0) {
            unsigned cum = 0;
            for (int bin = 255; bin >= 0; bin--) {
                unsigned c = hist[bin];
                if (cum + c >= need) {
                    *s_need = need - cum;
                    *s_pref = (pref << 8) | (unsigned)bin;
                    break;
                }
                cum += c;
            }
        }
        __syncthreads();
        pref = *s_pref; need = *s_need;
        __syncthreads();
    }
}

// =================== K_reduce (coalesced via K^T) ===========================
__global__ void k_kreduce(/* reads g_kt */) {
    __shared__ unsigned su[4096];
    __shared__ unsigned hist[256];
    __shared__ unsigned s_pref, s_need;
    __shared__ double red[256];
    int bd = blockIdx.x;
    int tid = threadIdx.x;
    const float* kp = g_kt + (size_t)bd * LK;
    for (int i = tid; i < 4096; i += 256) su[i] = f2sort(kp[i]);
    __syncthreads();
    radix_select(su, hist, &s_pref, &s_need, LSEL);
    unsigned tu = s_pref, need = s_need;
    double acc = 0.0;
    for (int i = tid; i < 4096; i += 256)
        if (su[i] > tu) acc += (double)sort2f(su[i]);
    red[tid] = acc;
    __syncthreads();
    for (int t = 128; t > 0; t >>= 1) {
        if (tid < t) red[tid] += red[tid + t];
        __syncthreads();
    }
    if (tid == 0)
        g_kreduce[bd] = (float)((red[0] + (double)need * (double)sort2f(tu)) / (double)LSEL);
}

// =================== value means ============================================
__global__ void k_meanpart(const float* __restrict__ values) {
    int b = blockIdx.y, j = blockIdx.x, d = threadIdx.x;
    const float* vp = values + ((size_t)b * LK + j * 128) * D_ + d;
    double s = 0.0;
#pragma unroll 8
    for (int r = 0; r < 128; r++) s += (double)vp[(size_t)r * D_];
    g_meanpart[((size_t)b * 32 + j) * D_ + d] = s;
}
__global__ void k_meanfin() {
    int b = blockIdx.x, d = threadIdx.x;
    double s = 0.0;
    for (int j = 0; j < 32; j++) s += g_meanpart[((size_t)b * 32 + j) * D_ + d];
    g_meanvals[b * D_ + d] = (float)(s / (double)LK);
}

// =================== sqk = Q . K_reduce (fp64) ===============================
__global__ void k_sqk(const float* __restrict__ queries) {
    __shared__ float kr[D_];
    int warp = threadIdx.x >> 5, lane = threadIdx.x & 31;
    int qflat = blockIdx.x * 8 + warp;
    int b = qflat >> 12;
    for (int i = threadIdx.x; i < D_; i += 256) kr[i] = g_kreduce[b * D_ + i];
    __syncthreads();
    const float* qp = queries + (size_t)qflat * D_;
    double acc = 0.0;
#pragma unroll
    for (int j = 0; j < 16; j++) {
        int d = lane + 32 * j;
        acc += (double)qp[d] * (double)kr[d];
    }
    for (int off = 16; off; off >>= 1) acc += __shfl_down_sync(0xffffffffu, acc, off);
    if (lane == 0) g_sqk[qflat] = (float)acc;
}

// =================== selection ==============================================
__global__ void k_thresh() {
    __shared__ unsigned su[4096];
    __shared__ unsigned hist[256];
    __shared__ unsigned s_pref, s_need;
    int b = blockIdx.x, tid = threadIdx.x;
    for (int i = tid; i < 4096; i += 256) su[i] = f2sort(g_sqk[b * LQ + i]);
    __syncthreads();
    radix_select(su, hist, &s_pref, &s_need, LSEL);
    if (tid == 0) {
        g_thresh[b] = sort2f(s_pref);
        g_selcnt[b] = 0;
    }
}

__global__ void k_compact() {
    int qflat = blockIdx.x * 256 + threadIdx.x;
    int b = qflat >> 12;
    if (g_sqk[qflat] >= g_thresh[b]) {
        int pos = atomicAdd(&g_selcnt[b], 1);
        if (pos < LSEL) g_selidx[b * LSEL + pos] = qflat & 4095;
    }
}

__global__ void k_fill(float* __restrict__ out) {
    int r = blockIdx.x, b = r >> 12;
    if (g_sqk[r] < g_thresh[b]) {
        const float4* mv = (const float4*)(g_meanvals + b * D_);
        float4* op = (float4*)(out + (size_t)r * D_);
        op[threadIdx.x] = mv[threadIdx.x];
    }
}

// =================== 2-pass fp16 tile compute ===============================
// stage: A @ st, Bh @ st+16K, Bl @ st+32K (each 128 rows x 128B, SW128)
// d += A*(Bh+Bl). warp grid 4(M) x 2(N); warp tile 32x64.
__device__ __forceinline__ void gemm_stage2(uint32_t st, int wm, int wn, int lane,
                                            float d[2][8][4]) {
    int rA = wm * 32 + (lane & 15);
    int kA = (lane >> 4) * 16;
    int rB = wn * 64 + (lane & 7) + ((lane >> 4) << 3);
    int kB = ((lane >> 3) & 1) * 16;
#pragma unroll
    for (int t = 0; t < 4; t++) {
        uint32_t a0[4], a1[4];
        LDSM4(a0, swaddr(st, rA, t * 32 + kA));
        LDSM4(a1, swaddr(st, rA + 16, t * 32 + kA));
#pragma unroll
        for (int p = 0; p < 4; p++) {
            uint32_t bh[4], bl[4];
            LDSM4(bh, swaddr(st + 16384, rB + p * 16, t * 32 + kB));
            LDSM4(bl, swaddr(st + 32768, rB + p * 16, t * 32 + kB));
            MMAH(d[0][2 * p],     a0, bh[0], bh[1]);
            MMAH(d[0][2 * p + 1], a0, bh[2], bh[3]);
            MMAH(d[1][2 * p],     a1, bh[0], bh[1]);
            MMAH(d[1][2 * p + 1], a1, bh[2], bh[3]);
            MMAH(d[0][2 * p],     a0, bl[0], bl[1]);
            MMAH(d[0][2 * p + 1], a0, bl[2], bl[3]);
            MMAH(d[1][2 * p],     a1, bl[0], bl[1]);
            MMAH(d[1][2 * p + 1], a1, bl[2], bl[3]);
        }
    }
}

#define SMEM_DYN (3 * 49152)

// =================== GEMM 1: E = exp(Qsel@K^T), row-sum partials ============
__global__ void __launch_bounds__(256, 1) k_gemm_qk() {
    extern __shared__ char dsm[];
    __shared__ int srow[128];
    __shared__ float zsh[2][128];
    uint32_t sb = smem_u32(dsm);
    int tid = threadIdx.x;
    int b = blockIdx.z, m0 = blockIdx.y * 128, n0 = blockIdx.x * 128;

    if (tid < 128) {
        int m = m0 + tid;
        srow[tid] = g_selidx[b * LSEL + (m < LSEL ? m : 0)];
    }
    __syncthreads();

    const __half* baseA = g_qh + (size_t)b * LQ * D_;
    const __half* baseBh = g_kh + ((size_t)b * LK + n0) * D_;
    const __half* baseBl = g_kl + ((size_t)b * LK + n0) * D_;

#define QK_FILL(s, k) do {                                                     \
    uint32_t st_ = sb + (s) * 49152;                                           \
    int k0_ = (k) * 64;                                                        \
    for (int idx = tid; idx < 3072; idx += 256) {                              \
        int tile_ = idx >> 10, r_ = (idx >> 3) & 127, seg_ = idx & 7;          \
        const __half* src_;                                                    \
        if (tile_ == 0)      src_ = baseA + (size_t)srow[r_] * D_ + k0_ + seg_ * 8; \
        else if (tile_ == 1) src_ = baseBh + (size_t)r_ * D_ + k0_ + seg_ * 8; \
        else                 src_ = baseBl + (size_t)r_ * D_ + k0_ + seg_ * 8; \
        CP_ASYNC16(swaddr(st_ + tile_ * 16384, r_, seg_ * 16), src_);          \
    } CP_COMMIT(); } while (0)

    QK_FILL(0, 0); QK_FILL(1, 1); QK_FILL(2, 2);

    int lane = tid & 31, w = tid >> 5, wm = w >> 1, wn = w & 1;
    float d[2][8][4] = {};

    for (int k = 0; k < 8; k++) {
        int s = k % 3;
        if (k == 7) { CP_WAIT0(); } else { CP_WAIT2(); }
        __syncthreads();
        gemm_stage2(sb + s * 49152, wm, wn, lane, d);
        __syncthreads();
        if (k + 3 < 8) QK_FILL(s, k + 3);
    }

    // epilogue: exp, row-sum partials, store E fp16
    float rs[2][2] = {};
#pragma unroll
    for (int i = 0; i < 2; i++)
#pragma unroll
        for (int j = 0; j < 8; j++) {
            d[i][j][0] = __expf(d[i][j][0]);
            d[i][j][1] = __expf(d[i][j][1]);
            d[i][j][2] = __expf(d[i][j][2]);
            d[i][j][3] = __expf(d[i][j][3]);
            rs[i][0] += d[i][j][0] + d[i][j][1];
            rs[i][1] += d[i][j][2] + d[i][j][3];
        }
#pragma unroll
    for (int i = 0; i < 2; i++)
#pragma unroll
        for (int h = 0; h < 2; h++) {
            rs[i][h] += __shfl_xor_sync(0xffffffffu, rs[i][h], 1);
            rs[i][h] += __shfl_xor_sync(0xffffffffu, rs[i][h], 2);
        }
    if ((lane & 3) == 0) {
        int rl = wm * 32 + (lane >> 2);
        zsh[wn][rl]      = rs[0][0];
        zsh[wn][rl + 8]  = rs[0][1];
        zsh[wn][rl + 16] = rs[1][0];
        zsh[wn][rl + 24] = rs[1][1];
    }

    int mBase = m0 + wm * 32, nBase = n0 + wn * 64;
#pragma unroll
    for (int i = 0; i < 2; i++) {
        int r = mBase + i * 16 + (lane >> 2);
#pragma unroll
        for (int j = 0; j < 8; j++) {
            int c = nBase + j * 8 + (lane & 3) * 2;
            if (r < LSEL)
                *(__half2*)(g_E + ((size_t)b * MPAD + r) * LK + c) =
                    __floats2half2_rn(d[i][j][0], d[i][j][1]);
            if (r + 8 < LSEL)
                *(__half2*)(g_E + ((size_t)b * MPAD + r + 8) * LK + c) =
                    __floats2half2_rn(d[i][j][2], d[i][j][3]);
        }
    }
    __syncthreads();
    if (tid < 128) {
        float z = zsh[0][tid] + zsh[1][tid];
        g_Zpart[(size_t)(b * MPAD + m0 + tid) * 32 + blockIdx.x] = z;
    }
}

// =================== Z reduction ============================================
__global__ void k_zsum() {
    int m = blockIdx.x * 256 + threadIdx.x;
    const float* p = g_Zpart + (size_t)m * 32;
    float s = 0.f;
#pragma unroll
    for (int i = 0; i < 32; i++) s += p[i];
    g_Z[m] = s;
}

// =================== GEMM 2: O = (E @ V)/Z, scatter =========================
__global__ void __launch_bounds__(256, 1) k_gemm_pv(float* __restrict__ out) {
    extern __shared__ char dsm[];
    __shared__ int srow[128];
    uint32_t sb = smem_u32(dsm);
    int tid = threadIdx.x;
    int b = blockIdx.z, m0 = blockIdx.y * 128, n0 = blockIdx.x * 128;

    if (tid < 128) {
        int m = m0 + tid;
        srow[tid] = g_selidx[b * LSEL + (m < LSEL ? m : 0)];
    }
    __syncthreads();

    const __half* baseA = g_E + ((size_t)b * MPAD + m0) * LK;
    const __half* baseBh = g_vth + ((size_t)b * D_ + n0) * LK;
    const __half* baseBl = g_vtl + ((size_t)b * D_ + n0) * LK;

#define PV_FILL(s, k) do {                                                     \
    uint32_t st_ = sb + (s) * 49152;                                           \
    int k0_ = (k) * 64;                                                        \
    for (int idx = tid; idx < 3072; idx += 256) {                              \
        int tile_ = idx >> 10, r_ = (idx >> 3) & 127, seg_ = idx & 7;          \
        const __half* src_;                                                    \
        if (tile_ == 0)      src_ = baseA + (size_t)r_ * LK + k0_ + seg_ * 8;  \
        else if (tile_ == 1) src_ = baseBh + (size_t)r_ * LK + k0_ + seg_ * 8; \
        else                 src_ = baseBl + (size_t)r_ * LK + k0_ + seg_ * 8; \
        CP_ASYNC16(swaddr(st_ + tile_ * 16384, r_, seg_ * 16), src_);          \
    } CP_COMMIT(); } while (0)

    PV_FILL(0, 0); PV_FILL(1, 1); PV_FILL(2, 2);

    int lane = tid & 31, w = tid >> 5, wm = w >> 1, wn = w & 1;
    float d[2][8][4] = {};

    for (int k = 0; k < 64; k++) {
        int s = k % 3;
        if (k == 63) { CP_WAIT0(); } else { CP_WAIT2(); }
        __syncthreads();
        gemm_stage2(sb + s * 49152, wm, wn, lane, d);
        __syncthreads();
        if (k + 3 < 64) PV_FILL(s, k + 3);
    }

    int nBase = n0 + wn * 64;
#pragma unroll
    for (int i = 0; i < 2; i++) {
        int lr = wm * 32 + i * 16 + (lane >> 2);
        int m = m0 + lr;
        float zi0 = 1.0f / g_Z[b * MPAD + m];
        float zi1 = 1.0f / g_Z[b * MPAD + m + 8];
        int q0 = srow[lr], q1 = srow[lr + 8];
#pragma unroll
        for (int j = 0; j < 8; j++) {
            int c = nBase + j * 8 + (lane & 3) * 2;
            if (m < LSEL)
                *(float2*)(out + ((size_t)b * LQ + q0) * D_ + c) =
                    float2{d[i][j][0] * zi0, d[i][j][1] * zi0};
            if (m + 8 < LSEL)
                *(float2*)(out + ((size_t)b * LQ + q1) * D_ + c) =
                    float2{d[i][j][2] * zi1, d[i][j][3] * zi1};
        }
    }
}

// =================== launch ==================================================
extern "C" void kernel_launch(void* const* d_in, const int* in_sizes, int n_in,
                              void* d_out, int out_size) {
    const float* q = (const float*)d_in[0];
    const float* k = (const float*)d_in[1];
    const float* v = (const float*)d_in[2];
    float* out = (float*)d_out;

    cudaFuncSetAttribute(k_gemm_qk, cudaFuncAttributeMaxDynamicSharedMemorySize, SMEM_DYN);
    cudaFuncSetAttribute(k_gemm_pv, cudaFuncAttributeMaxDynamicSharedMemorySize, SMEM_DYN);

    k_split_q<<<16384, 256>>>((const float4*)q);
    k_split_k<<<16384, 256>>>((const float4*)k);
    k_split_vt<<<dim3(16, 128, 8), dim3(32, 8)>>>(v);
    k_transpose<<<dim3(16, 128, 8), dim3(32, 8)>>>(k);

    k_kreduce<<<B_ * D_, 256>>>();
    k_meanpart<<<dim3(32, B_), 512>>>(v);
    k_meanfin<<<B_, 512>>>();
    k_sqk<<<B_ * LQ / 8, 256>>>(q);
    k_thresh<<<B_, 256>>>();
    k_compact<<<B_ * LQ / 256, 256>>>();
    k_fill<<<B_ * LQ, 128>>>(out);

    dim3 g1(LK / 128, (LSEL + 127) / 128, B_);   // 32 x 22 x 8
    k_gemm_qk<<<g1, 256, SMEM_DYN>>>();

    k_zsum<<<B_ * MPAD / 256, 256>>>();

    dim3 g2(D_ / 128, (LSEL + 127) / 128, B_);   // 4 x 22 x 8
    k_gemm_pv<<<g2, 256, SMEM_DYN>>>(out);
}

// round 6
// speedup vs baseline: 7.7949x; 1.8664x over previous
#include <cuda_runtime.h>
#include <cuda_fp16.h>
#include <cstdint>

#define B_    8
#define LQ    4096
#define LK    4096
#define D_    512
#define LSEL  2744
#define MPAD  2816
#define SCALE 0.04419417382415922f   // 1/sqrt(512)

// ============================ device scratch ================================
__device__ __half g_qh[B_ * LQ * D_];           // Q*SCALE fp16
__device__ __half g_kh[B_ * LK * D_];           // K fp16
__device__ __half g_vth[B_ * D_ * LK];          // V^T fp16 [b][d][k]
__device__ __half g_E[(size_t)B_ * MPAD * LK];  // exp(S) fp16 [b][m][k]
__device__ float  g_kt[(size_t)B_ * D_ * LK];   // K^T fp32 [b][d][k]
__device__ float  g_Zpart[B_ * MPAD * 32];
__device__ float  g_Z[B_ * MPAD];
__device__ float  g_kreduce[B_ * D_];
__device__ double g_meanpart[B_ * 32 * D_];
__device__ float  g_meanvals[B_ * D_];
__device__ float  g_sqk[B_ * LQ];
__device__ float  g_thresh[B_];
__device__ int    g_selidx[B_ * LSEL];
__device__ int    g_selcnt[B_];

// ============================ PTX helpers ===================================
__device__ __forceinline__ uint32_t smem_u32(const void* p) {
    uint32_t a;
    asm("{ .reg .u64 t; cvta.to.shared.u64 t, %1; cvt.u32.u64 %0, t; }" : "=r"(a) : "l"(p));
    return a;
}

#define CP_ASYNC16(dst, src) \
    asm volatile("cp.async.cg.shared.global [%0], [%1], 16;" :: "r"(dst), "l"(src) : "memory")
#define CP_COMMIT() asm volatile("cp.async.commit_group;" ::: "memory")
#define CP_WAIT2()  asm volatile("cp.async.wait_group 2;" ::: "memory")
#define CP_WAIT0()  asm volatile("cp.async.wait_group 0;" ::: "memory")

#define LDSM4(r, a) \
    asm volatile("ldmatrix.sync.aligned.m8n8.x4.shared.b16 {%0,%1,%2,%3}, [%4];" \
        : "=r"((r)[0]), "=r"((r)[1]), "=r"((r)[2]), "=r"((r)[3]) : "r"(a))

#define MMAH(d, a, b0, b1) \
    asm volatile("mma.sync.aligned.m16n8k16.row.col.f32.f16.f16.f32 " \
        "{%0,%1,%2,%3}, {%4,%5,%6,%7}, {%8,%9}, {%0,%1,%2,%3};" \
        : "+f"((d)[0]), "+f"((d)[1]), "+f"((d)[2]), "+f"((d)[3]) \
        : "r"((a)[0]), "r"((a)[1]), "r"((a)[2]), "r"((a)[3]), "r"(b0), "r"(b1))

// swizzled addr inside one 128-row x 128-byte tile (SW128)
__device__ __forceinline__ uint32_t swaddr(uint32_t base, int row, int kb) {
    uint32_t o = (uint32_t)(row * 128 + kb);
    return base + (o ^ ((o >> 3) & 0x70));
}

__device__ __forceinline__ unsigned f2sort(float f) {
    unsigned u = __float_as_uint(f);
    return (u & 0x80000000u) ? ~u : (u | 0x80000000u);
}
__device__ __forceinline__ float sort2f(unsigned u) {
    unsigned fb = (u & 0x80000000u) ? (u ^ 0x80000000u) : ~u;
    return __uint_as_float(fb);
}

// =================== splits ==================================================
__global__ void k_split_q(const float4* __restrict__ src) {
    size_t i = (size_t)blockIdx.x * 256 + threadIdx.x;
    float4 v = src[i];
    __half2* dh = (__half2*)g_qh;
    dh[2 * i]     = __floats2half2_rn(v.x * SCALE, v.y * SCALE);
    dh[2 * i + 1] = __floats2half2_rn(v.z * SCALE, v.w * SCALE);
}

__global__ void k_split_k(const float4* __restrict__ src) {
    size_t i = (size_t)blockIdx.x * 256 + threadIdx.x;
    float4 v = src[i];
    ((__half2*)g_kh)[2 * i]     = __floats2half2_rn(v.x, v.y);
    ((__half2*)g_kh)[2 * i + 1] = __floats2half2_rn(v.z, v.w);
}

__global__ void k_split_vt(const float* __restrict__ v) {
    __shared__ float t[32][33];
    int b = blockIdx.z, d0 = blockIdx.x * 32, k0 = blockIdx.y * 32;
    int tx = threadIdx.x, ty = threadIdx.y;
#pragma unroll
    for (int j = 0; j < 4; j++)
        t[ty + 8 * j][tx] = v[((size_t)b * LK + k0 + ty + 8 * j) * D_ + d0 + tx];
    __syncthreads();
#pragma unroll
    for (int j = 0; j < 4; j++)
        g_vth[((size_t)b * D_ + d0 + ty + 8 * j) * LK + k0 + tx] =
            __float2half_rn(t[tx][ty + 8 * j]);
}

__global__ void k_transpose(const float* __restrict__ keys) {
    __shared__ float t[32][33];
    int b = blockIdx.z, d0 = blockIdx.x * 32, k0 = blockIdx.y * 32;
    int tx = threadIdx.x, ty = threadIdx.y;
#pragma unroll
    for (int j = 0; j < 4; j++)
        t[ty + 8 * j][tx] = keys[((size_t)b * LK + k0 + ty + 8 * j) * D_ + d0 + tx];
    __syncthreads();
#pragma unroll
    for (int j = 0; j < 4; j++)
        g_kt[((size_t)b * D_ + d0 + ty + 8 * j) * LK + k0 + tx] = t[tx][ty + 8 * j];
}

// =================== radix select: k-th largest of 4096 =====================
__device__ void radix_select(unsigned* su, unsigned* hist,
                             unsigned* s_pref, unsigned* s_need, int want) {
    int tid = threadIdx.x;
    if (tid == 0) { *s_pref = 0; *s_need = (unsigned)want; }
    __syncthreads();
    unsigned pref = 0, need = (unsigned)want;
    for (int pass = 3; pass >= 0; pass--) {
        if (tid < 256) hist[tid] = 0;
        __syncthreads();
        for (int i = tid; i < 4096; i += 256) {
            unsigned u = su[i];
            unsigned hi = (pass == 3) ? 0u : (u >> ((pass + 1) * 8));
            if (hi == pref) atomicAdd(&hist[(u >> (pass * 8)) & 255], 1);
        }
        __syncthreads();
        if (tid == 0) {
            unsigned cum = 0;
            for (int bin = 255; bin >= 0; bin--) {
                unsigned c = hist[bin];
                if (cum + c >= need) {
                    *s_need = need - cum;
                    *s_pref = (pref << 8) | (unsigned)bin;
                    break;
                }
                cum += c;
            }
        }
        __syncthreads();
        pref = *s_pref; need = *s_need;
        __syncthreads();
    }
}

// =================== K_reduce (coalesced via K^T) ===========================
__global__ void k_kreduce() {
    __shared__ unsigned su[4096];
    __shared__ unsigned hist[256];
    __shared__ unsigned s_pref, s_need;
    __shared__ double red[256];
    int bd = blockIdx.x;
    int tid = threadIdx.x;
    const float* kp = g_kt + (size_t)bd * LK;
    for (int i = tid; i < 4096; i += 256) su[i] = f2sort(kp[i]);
    __syncthreads();
    radix_select(su, hist, &s_pref, &s_need, LSEL);
    unsigned tu = s_pref, need = s_need;
    double acc = 0.0;
    for (int i = tid; i < 4096; i += 256)
        if (su[i] > tu) acc += (double)sort2f(su[i]);
    red[tid] = acc;
    __syncthreads();
    for (int t = 128; t > 0; t >>= 1) {
        if (tid < t) red[tid] += red[tid + t];
        __syncthreads();
    }
    if (tid == 0)
        g_kreduce[bd] = (float)((red[0] + (double)need * (double)sort2f(tu)) / (double)LSEL);
}

// =================== value means ============================================
__global__ void k_meanpart(const float* __restrict__ values) {
    int b = blockIdx.y, j = blockIdx.x, d = threadIdx.x;
    const float* vp = values + ((size_t)b * LK + j * 128) * D_ + d;
    double s = 0.0;
#pragma unroll 8
    for (int r = 0; r < 128; r++) s += (double)vp[(size_t)r * D_];
    g_meanpart[((size_t)b * 32 + j) * D_ + d] = s;
}
__global__ void k_meanfin() {
    int b = blockIdx.x, d = threadIdx.x;
    double s = 0.0;
    for (int j = 0; j < 32; j++) s += g_meanpart[((size_t)b * 32 + j) * D_ + d];
    g_meanvals[b * D_ + d] = (float)(s / (double)LK);
}

// =================== sqk = Q . K_reduce (fp64) ===============================
__global__ void k_sqk(const float* __restrict__ queries) {
    __shared__ float kr[D_];
    int warp = threadIdx.x >> 5, lane = threadIdx.x & 31;
    int qflat = blockIdx.x * 8 + warp;
    int b = qflat >> 12;
    for (int i = threadIdx.x; i < D_; i += 256) kr[i] = g_kreduce[b * D_ + i];
    __syncthreads();
    const float* qp = queries + (size_t)qflat * D_;
    double acc = 0.0;
#pragma unroll
    for (int j = 0; j < 16; j++) {
        int d = lane + 32 * j;
        acc += (double)qp[d] * (double)kr[d];
    }
    for (int off = 16; off; off >>= 1) acc += __shfl_down_sync(0xffffffffu, acc, off);
    if (lane == 0) g_sqk[qflat] = (float)acc;
}

// =================== selection ==============================================
__global__ void k_thresh() {
    __shared__ unsigned su[4096];
    __shared__ unsigned hist[256];
    __shared__ unsigned s_pref, s_need;
    int b = blockIdx.x, tid = threadIdx.x;
    for (int i = tid; i < 4096; i += 256) su[i] = f2sort(g_sqk[b * LQ + i]);
    __syncthreads();
    radix_select(su, hist, &s_pref, &s_need, LSEL);
    if (tid == 0) {
        g_thresh[b] = sort2f(s_pref);
        g_selcnt[b] = 0;
    }
}

__global__ void k_compact() {
    int qflat = blockIdx.x * 256 + threadIdx.x;
    int b = qflat >> 12;
    if (g_sqk[qflat] >= g_thresh[b]) {
        int pos = atomicAdd(&g_selcnt[b], 1);
        if (pos < LSEL) g_selidx[b * LSEL + pos] = qflat & 4095;
    }
}

__global__ void k_fill(float* __restrict__ out) {
    int r = blockIdx.x, b = r >> 12;
    if (g_sqk[r] < g_thresh[b]) {
        const float4* mv = (const float4*)(g_meanvals + b * D_);
        float4* op = (float4*)(out + (size_t)r * D_);
        op[threadIdx.x] = mv[threadIdx.x];
    }
}

// =================== 1-pass fp16 tile compute ===============================
// stage: A @ st, B @ st+16K (each 128 rows x 128B, SW128). d += A*B.
// warp grid 4(M) x 2(N); warp tile 32x64.
__device__ __forceinline__ void gemm_stage1(uint32_t st, int wm, int wn, int lane,
                                            float d[2][8][4]) {
    int rA = wm * 32 + (lane & 15);
    int kA = (lane >> 4) * 16;
    int rB = wn * 64 + (lane & 7) + ((lane >> 4) << 3);
    int kB = ((lane >> 3) & 1) * 16;
#pragma unroll
    for (int t = 0; t < 4; t++) {
        uint32_t a0[4], a1[4];
        LDSM4(a0, swaddr(st, rA, t * 32 + kA));
        LDSM4(a1, swaddr(st, rA + 16, t * 32 + kA));
#pragma unroll
        for (int p = 0; p < 4; p++) {
            uint32_t bh[4];
            LDSM4(bh, swaddr(st + 16384, rB + p * 16, t * 32 + kB));
            MMAH(d[0][2 * p],     a0, bh[0], bh[1]);
            MMAH(d[0][2 * p + 1], a0, bh[2], bh[3]);
            MMAH(d[1][2 * p],     a1, bh[0], bh[1]);
            MMAH(d[1][2 * p + 1], a1, bh[2], bh[3]);
        }
    }
}

#define SMEM_DYN (3 * 32768)

// =================== GEMM 1: E = exp(Qsel@K^T), row-sum partials ============
__global__ void __launch_bounds__(256, 2) k_gemm_qk() {
    extern __shared__ char dsm[];
    __shared__ int srow[128];
    __shared__ float zsh[2][128];
    uint32_t sb = smem_u32(dsm);
    int tid = threadIdx.x;
    int b = blockIdx.z, m0 = blockIdx.y * 128, n0 = blockIdx.x * 128;

    if (tid < 128) {
        int m = m0 + tid;
        srow[tid] = g_selidx[b * LSEL + (m < LSEL ? m : 0)];
    }
    __syncthreads();

    const __half* baseA = g_qh + (size_t)b * LQ * D_;
    const __half* baseB = g_kh + ((size_t)b * LK + n0) * D_;

#define QK_FILL(s, k) do {                                                     \
    uint32_t st_ = sb + (s) * 32768;                                           \
    int k0_ = (k) * 64;                                                        \
    for (int idx = tid; idx < 2048; idx += 256) {                              \
        int tile_ = idx >> 10, r_ = (idx >> 3) & 127, seg_ = idx & 7;          \
        const __half* src_ = (tile_ == 0)                                      \
            ? baseA + (size_t)srow[r_] * D_ + k0_ + seg_ * 8                   \
            : baseB + (size_t)r_ * D_ + k0_ + seg_ * 8;                        \
        CP_ASYNC16(swaddr(st_ + tile_ * 16384, r_, seg_ * 16), src_);          \
    } CP_COMMIT(); } while (0)

    QK_FILL(0, 0); QK_FILL(1, 1); QK_FILL(2, 2);

    int lane = tid & 31, w = tid >> 5, wm = w >> 1, wn = w & 1;
    float d[2][8][4] = {};

    for (int k = 0; k < 8; k++) {
        int s = k % 3;
        if (k == 7) { CP_WAIT0(); } else { CP_WAIT2(); }
        __syncthreads();
        gemm_stage1(sb + s * 32768, wm, wn, lane, d);
        __syncthreads();
        if (k + 3 < 8) QK_FILL(s, k + 3);
    }

    // epilogue: exp, row-sum partials, store E fp16
    float rs[2][2] = {};
#pragma unroll
    for (int i = 0; i < 2; i++)
#pragma unroll
        for (int j = 0; j < 8; j++) {
            d[i][j][0] = __expf(d[i][j][0]);
            d[i][j][1] = __expf(d[i][j][1]);
            d[i][j][2] = __expf(d[i][j][2]);
            d[i][j][3] = __expf(d[i][j][3]);
            rs[i][0] += d[i][j][0] + d[i][j][1];
            rs[i][1] += d[i][j][2] + d[i][j][3];
        }
#pragma unroll
    for (int i = 0; i < 2; i++)
#pragma unroll
        for (int h = 0; h < 2; h++) {
            rs[i][h] += __shfl_xor_sync(0xffffffffu, rs[i][h], 1);
            rs[i][h] += __shfl_xor_sync(0xffffffffu, rs[i][h], 2);
        }
    if ((lane & 3) == 0) {
        int rl = wm * 32 + (lane >> 2);
        zsh[wn][rl]      = rs[0][0];
        zsh[wn][rl + 8]  = rs[0][1];
        zsh[wn][rl + 16] = rs[1][0];
        zsh[wn][rl + 24] = rs[1][1];
    }

    int mBase = m0 + wm * 32, nBase = n0 + wn * 64;
#pragma unroll
    for (int i = 0; i < 2; i++) {
        int r = mBase + i * 16 + (lane >> 2);
#pragma unroll
        for (int j = 0; j < 8; j++) {
            int c = nBase + j * 8 + (lane & 3) * 2;
            if (r < LSEL)
                *(__half2*)(g_E + ((size_t)b * MPAD + r) * LK + c) =
                    __floats2half2_rn(d[i][j][0], d[i][j][1]);
            if (r + 8 < LSEL)
                *(__half2*)(g_E + ((size_t)b * MPAD + r + 8) * LK + c) =
                    __floats2half2_rn(d[i][j][2], d[i][j][3]);
        }
    }
    __syncthreads();
    if (tid < 128) {
        float z = zsh[0][tid] + zsh[1][tid];
        g_Zpart[(size_t)(b * MPAD + m0 + tid) * 32 + blockIdx.x] = z;
    }
}

// =================== Z reduction ============================================
__global__ void k_zsum() {
    int m = blockIdx.x * 256 + threadIdx.x;
    const float* p = g_Zpart + (size_t)m * 32;
    float s = 0.f;
#pragma unroll
    for (int i = 0; i < 32; i++) s += p[i];
    g_Z[m] = s;
}

// =================== GEMM 2: O = (E @ V)/Z, scatter =========================
__global__ void __launch_bounds__(256, 2) k_gemm_pv(float* __restrict__ out) {
    extern __shared__ char dsm[];
    __shared__ int srow[128];
    uint32_t sb = smem_u32(dsm);
    int tid = threadIdx.x;
    int b = blockIdx.z, m0 = blockIdx.y * 128, n0 = blockIdx.x * 128;

    if (tid < 128) {
        int m = m0 + tid;
        srow[tid] = g_selidx[b * LSEL + (m < LSEL ? m : 0)];
    }
    __syncthreads();

    const __half* baseA = g_E + ((size_t)b * MPAD + m0) * LK;
    const __half* baseB = g_vth + ((size_t)b * D_ + n0) * LK;

#define PV_FILL(s, k) do {                                                     \
    uint32_t st_ = sb + (s) * 32768;                                           \
    int k0_ = (k) * 64;                                                        \
    for (int idx = tid; idx < 2048; idx += 256) {                              \
        int tile_ = idx >> 10, r_ = (idx >> 3) & 127, seg_ = idx & 7;          \
        const __half* src_ = (tile_ == 0)                                      \
            ? baseA + (size_t)r_ * LK + k0_ + seg_ * 8                         \
            : baseB + (size_t)r_ * LK + k0_ + seg_ * 8;                        \
        CP_ASYNC16(swaddr(st_ + tile_ * 16384, r_, seg_ * 16), src_);          \
    } CP_COMMIT(); } while (0)

    PV_FILL(0, 0); PV_FILL(1, 1); PV_FILL(2, 2);

    int lane = tid & 31, w = tid >> 5, wm = w >> 1, wn = w & 1;
    float d[2][8][4] = {};

    for (int k = 0; k < 64; k++) {
        int s = k % 3;
        if (k == 63) { CP_WAIT0(); } else { CP_WAIT2(); }
        __syncthreads();
        gemm_stage1(sb + s * 32768, wm, wn, lane, d);
        __syncthreads();
        if (k + 3 < 64) PV_FILL(s, k + 3);
    }

    int nBase = n0 + wn * 64;
#pragma unroll
    for (int i = 0; i < 2; i++) {
        int lr = wm * 32 + i * 16 + (lane >> 2);
        int m = m0 + lr;
        float zi0 = 1.0f / g_Z[b * MPAD + m];
        float zi1 = 1.0f / g_Z[b * MPAD + m + 8];
        int q0 = srow[lr], q1 = srow[lr + 8];
#pragma unroll
        for (int j = 0; j < 8; j++) {
            int c = nBase + j * 8 + (lane & 3) * 2;
            if (m < LSEL)
                *(float2*)(out + ((size_t)b * LQ + q0) * D_ + c) =
                    float2{d[i][j][0] * zi0, d[i][j][1] * zi0};
            if (m + 8 < LSEL)
                *(float2*)(out + ((size_t)b * LQ + q1) * D_ + c) =
                    float2{d[i][j][2] * zi1, d[i][j][3] * zi1};
        }
    }
}

// =================== launch ==================================================
extern "C" void kernel_launch(void* const* d_in, const int* in_sizes, int n_in,
                              void* d_out, int out_size) {
    const float* q = (const float*)d_in[0];
    const float* k = (const float*)d_in[1];
    const float* v = (const float*)d_in[2];
    float* out = (float*)d_out;

    cudaFuncSetAttribute(k_gemm_qk, cudaFuncAttributeMaxDynamicSharedMemorySize, SMEM_DYN);
    cudaFuncSetAttribute(k_gemm_pv, cudaFuncAttributeMaxDynamicSharedMemorySize, SMEM_DYN);

    k_split_q<<<16384, 256>>>((const float4*)q);
    k_split_k<<<16384, 256>>>((const float4*)k);
    k_split_vt<<<dim3(16, 128, 8), dim3(32, 8)>>>(v);
    k_transpose<<<dim3(16, 128, 8), dim3(32, 8)>>>(k);

    k_kreduce<<<B_ * D_, 256>>>();
    k_meanpart<<<dim3(32, B_), 512>>>(v);
    k_meanfin<<<B_, 512>>>();
    k_sqk<<<B_ * LQ / 8, 256>>>(q);
    k_thresh<<<B_, 256>>>();
    k_compact<<<B_ * LQ / 256, 256>>>();
    k_fill<<<B_ * LQ, 128>>>(out);

    dim3 g1(LK / 128, (LSEL + 127) / 128, B_);   // 32 x 22 x 8
    k_gemm_qk<<<g1, 256, SMEM_DYN>>>();

    k_zsum<<<B_ * MPAD / 256, 256>>>();

    dim3 g2(D_ / 128, (LSEL + 127) / 128, B_);   // 4 x 22 x 8
    k_gemm_pv<<<g2, 256, SMEM_DYN>>>(out);
}